// round 7
// baseline (speedup 1.0000x reference)
#include <cuda_runtime.h>

// CreatePairsSum, register-blocked version (finer CTA granularity).
// Thread layout: 128 threads/CTA = 8 batch rows x 16 feature-chunks (float4).
// Each thread loads the 10 jet values of its chunk into registers (compulsory
// read traffic only, coalesced), then writes the 45 pair sums directly.
// Pair index is computed arithmetically from (i, j, n):
//   combinations(range(n), 2) lexicographic:  p = i*n - i(i+1)/2 + (j-i-1),
//   valid iff j < n.  Tail p in [C(n,2), 45) is zero-filled.
//
// Inputs (metadata order):
//   d_in[0]: inputs    float32 [16384, 10, 64]
//   d_in[1]: dict_vals int32   [9, 45, 2]   (unused -- ordering is arithmetic)
//   d_in[2]: jet_num   int32   [16384]
// Output: float32, pairs_sum [16384, 45, 64] then pairs_num [16384, 1].

#define BATCH      16384
#define MAX_JETS   10
#define MAX_PAIRS  45
#define N_FEAT     64
#define F4_PER_ROW (N_FEAT / 4)                 // 16 float4 per jet row
#define IN_F4      (MAX_JETS * F4_PER_ROW)      // 160 float4 per batch row
#define OUT_F4     (MAX_PAIRS * F4_PER_ROW)     // 720 float4 per batch row
#define ROWS_PER_CTA 8
#define THREADS    (ROWS_PER_CTA * F4_PER_ROW)  // 128

__global__ __launch_bounds__(THREADS)
void create_pairs_sum_kernel(const float4* __restrict__ in,      // [BATCH * IN_F4]
                             const int*    __restrict__ jet_num, // [BATCH]
                             float4*       __restrict__ out_sum, // [BATCH * OUT_F4]
                             float*        __restrict__ out_num) // [BATCH]
{
    const int tid = threadIdx.x;
    const int c   = tid & (F4_PER_ROW - 1);          // feature chunk 0..15
    const int r   = tid >> 4;                        // local row 0..7
    const int b   = blockIdx.x * ROWS_PER_CTA + r;   // global batch row

    const int n = __ldg(&jet_num[b]);
    const int T = (n * (n - 1)) >> 1;                // C(n,2)

    if (c == 0) {
        out_num[b] = (float)T;
    }

    // Load all 10 jet values for this (row, chunk) into registers.
    const float4* __restrict__ src = in + (long long)b * IN_F4 + c;
    float4 jet[MAX_JETS];
    #pragma unroll
    for (int i = 0; i < MAX_JETS; i++) {
        jet[i] = __ldg(&src[i * F4_PER_ROW]);
    }

    float4* __restrict__ dst = out_sum + (long long)b * OUT_F4 + c;

    // Emit all valid pairs in combinations(range(n)) lexicographic order.
    #pragma unroll
    for (int i = 0; i < MAX_JETS - 1; i++) {
        // base index for block i: i*n - i(i+1)/2 - (i+1), then + j
        const int base = i * n - ((i * (i + 1)) >> 1) - (i + 1);
        #pragma unroll
        for (int j = i + 1; j < MAX_JETS; j++) {
            if (j < n) {
                const int p = base + j;              // pair index for this n
                float4 v;
                v.x = jet[i].x + jet[j].x;
                v.y = jet[i].y + jet[j].y;
                v.z = jet[i].z + jet[j].z;
                v.w = jet[i].w + jet[j].w;
                dst[p * F4_PER_ROW] = v;
            }
        }
    }

    // Zero-fill invalid tail (output buffer is poisoned, must be written).
    const float4 z = make_float4(0.f, 0.f, 0.f, 0.f);
    for (int p = T; p < MAX_PAIRS; p++) {
        dst[p * F4_PER_ROW] = z;
    }
}

extern "C" void kernel_launch(void* const* d_in, const int* in_sizes, int n_in,
                              void* d_out, int out_size)
{
    const float4* in      = (const float4*)d_in[0];
    const int*    jet_num = (const int*)d_in[2];

    float* out = (float*)d_out;
    float4* out_sum = (float4*)out;                                   // BATCH*45*64 floats
    float*  out_num = out + (long long)BATCH * MAX_PAIRS * N_FEAT;    // BATCH floats

    create_pairs_sum_kernel<<<BATCH / ROWS_PER_CTA, THREADS>>>(in, jet_num,
                                                               out_sum, out_num);
}

// round 9
// speedup vs baseline: 1.1131x; 1.1131x over previous
#include <cuda_runtime.h>

// CreatePairsSum, register-blocked + streaming stores.
// Thread layout: 256 threads/CTA = 16 batch rows x 16 feature-chunks (float4).
// Each thread loads the 10 jet values of its chunk into registers (compulsory
// read traffic only, coalesced), then writes the 45 pair sums directly with
// __stcs (evict-first) since the output has no reuse -- avoids thrashing L2
// against the read stream.
// Pair index is computed arithmetically from (i, j, n):
//   combinations(range(n), 2) lexicographic:  p = i*n - i(i+1)/2 + (j-i-1),
//   valid iff j < n.  Tail p in [C(n,2), 45) is zero-filled.
//
// Inputs (metadata order):
//   d_in[0]: inputs    float32 [16384, 10, 64]
//   d_in[1]: dict_vals int32   [9, 45, 2]   (unused -- ordering is arithmetic)
//   d_in[2]: jet_num   int32   [16384]
// Output: float32, pairs_sum [16384, 45, 64] then pairs_num [16384, 1].

#define BATCH      16384
#define MAX_JETS   10
#define MAX_PAIRS  45
#define N_FEAT     64
#define F4_PER_ROW (N_FEAT / 4)                 // 16 float4 per jet row
#define IN_F4      (MAX_JETS * F4_PER_ROW)      // 160 float4 per batch row
#define OUT_F4     (MAX_PAIRS * F4_PER_ROW)     // 720 float4 per batch row
#define ROWS_PER_CTA 16
#define THREADS    (ROWS_PER_CTA * F4_PER_ROW)  // 256

__global__ __launch_bounds__(THREADS)
void create_pairs_sum_kernel(const float4* __restrict__ in,      // [BATCH * IN_F4]
                             const int*    __restrict__ jet_num, // [BATCH]
                             float4*       __restrict__ out_sum, // [BATCH * OUT_F4]
                             float*        __restrict__ out_num) // [BATCH]
{
    const int tid = threadIdx.x;
    const int c   = tid & (F4_PER_ROW - 1);          // feature chunk 0..15
    const int r   = tid >> 4;                        // local row 0..15
    const int b   = blockIdx.x * ROWS_PER_CTA + r;   // global batch row

    const int n = __ldg(&jet_num[b]);
    const int T = (n * (n - 1)) >> 1;                // C(n,2)

    if (c == 0) {
        out_num[b] = (float)T;
    }

    // Load all 10 jet values for this (row, chunk) into registers.
    const float4* __restrict__ src = in + (long long)b * IN_F4 + c;
    float4 jet[MAX_JETS];
    #pragma unroll
    for (int i = 0; i < MAX_JETS; i++) {
        jet[i] = __ldg(&src[i * F4_PER_ROW]);
    }

    float4* __restrict__ dst = out_sum + (long long)b * OUT_F4 + c;

    // Emit all valid pairs in combinations(range(n)) lexicographic order.
    #pragma unroll
    for (int i = 0; i < MAX_JETS - 1; i++) {
        // base index for block i: i*n - i(i+1)/2 - (i+1), then + j
        const int base = i * n - ((i * (i + 1)) >> 1) - (i + 1);
        #pragma unroll
        for (int j = i + 1; j < MAX_JETS; j++) {
            if (j < n) {
                const int p = base + j;              // pair index for this n
                float4 v;
                v.x = jet[i].x + jet[j].x;
                v.y = jet[i].y + jet[j].y;
                v.z = jet[i].z + jet[j].z;
                v.w = jet[i].w + jet[j].w;
                __stcs(&dst[p * F4_PER_ROW], v);     // streaming store, no reuse
            }
        }
    }

    // Zero-fill invalid tail (output buffer is poisoned, must be written).
    const float4 z = make_float4(0.f, 0.f, 0.f, 0.f);
    for (int p = T; p < MAX_PAIRS; p++) {
        __stcs(&dst[p * F4_PER_ROW], z);
    }
}

extern "C" void kernel_launch(void* const* d_in, const int* in_sizes, int n_in,
                              void* d_out, int out_size)
{
    const float4* in      = (const float4*)d_in[0];
    const int*    jet_num = (const int*)d_in[2];

    float* out = (float*)d_out;
    float4* out_sum = (float4*)out;                                   // BATCH*45*64 floats
    float*  out_num = out + (long long)BATCH * MAX_PAIRS * N_FEAT;    // BATCH floats

    create_pairs_sum_kernel<<<BATCH / ROWS_PER_CTA, THREADS>>>(in, jet_num,
                                                               out_sum, out_num);
}